// round 2
// baseline (speedup 1.0000x reference)
#include <cuda_runtime.h>
#include <cuda_bf16.h>
#include <math.h>

// ---------------------------------------------------------------------------
// ScatterLoss: loss depends only on per-class statistics.
//   s_c = sum of rows with label c   (C x D)
//   total = sum over all rows        (D)
//   v_c[d] = alpha_c * s_c[d] - beta_c * total[d] + EPS
//     alpha_c = 1/cnt_c + 1/(N-cnt_c),  beta_c = 1/(N-cnt_c)
//   loss = (1/N) * sum_c cnt_c * max(1 - ||v_c||, 0)^2
// ---------------------------------------------------------------------------

#define NN 65536
#define DD 512
#define CC 512
#define EPSV 1e-6f
#define MARGINV 1.0f

#define COLS 32              // columns per chunk (128B per warp row-load)
#define CHUNKS (DD / COLS)   // 16
#define YS 24                // row splits (16*24 = 384 blocks)
#define RPB ((NN + YS - 1) / YS)   // 2731
#define NW 8                 // warps per block
#define UNROLL 8
#define SEG_SMEM (CC * COLS * 4)   // 64 KB

// Scratch (device globals: allocation-free per harness rules)
__device__ float g_part[(size_t)YS * CC * DD];  // 24 MB partial class sums
__device__ float g_sums[CC * DD];               // 1 MB final class sums
__device__ float g_total[DD];
__device__ int   g_cnts[CC];
__device__ float g_loss;
__device__ int   g_lab_stride;                  // 1 = int32 labels, 2 = int64

// --- init: zero accumulators + detect label dtype -------------------------
__global__ void kInit(const int* __restrict__ lab32) {
    int t = threadIdx.x;
    if (t < DD) g_total[t] = 0.f;
    if (t < CC) g_cnts[t] = 0;
    if (t == 0) g_loss = 0.f;
    // int64 little-endian: element i -> lab32[2i] (lo), lab32[2i+1] (hi==0).
    // For int32 random labels in [0,512), 128 consecutive odd words all being
    // zero is impossible in practice (prob ~ 512^-128).
    int nz = (t < 128) ? lab32[2 * t + 1] : 0;
    int any = __syncthreads_or(nz);
    if (t == 0) g_lab_stride = any ? 1 : 2;
}

// --- histogram of labels ---------------------------------------------------
__global__ void kHist(const int* __restrict__ lab32) {
    __shared__ int h[CC];
    for (int i = threadIdx.x; i < CC; i += blockDim.x) h[i] = 0;
    __syncthreads();
    const int stride = g_lab_stride;
    for (int i = blockIdx.x * blockDim.x + threadIdx.x; i < NN;
         i += gridDim.x * blockDim.x) {
        atomicAdd(&h[lab32[i * stride]], 1);
    }
    __syncthreads();
    for (int i = threadIdx.x; i < CC; i += blockDim.x)
        if (h[i]) atomicAdd(&g_cnts[i], h[i]);
}

// --- segment sums: the HBM-bound core (reads all 128 MB once) -------------
__global__ void kSegSum(const float* __restrict__ out,
                        const int* __restrict__ lab32) {
    extern __shared__ float tbl[];   // [CC][COLS]
    for (int i = threadIdx.x; i < CC * COLS; i += blockDim.x) tbl[i] = 0.f;
    __syncthreads();

    const int stride = g_lab_stride;
    const int col0 = blockIdx.x * COLS;
    const int r0 = blockIdx.y * RPB;
    const int r1 = (r0 + RPB < NN) ? (r0 + RPB) : NN;
    const int lane = threadIdx.x & 31;
    const int warp = threadIdx.x >> 5;
    const float* base = out + col0 + lane;

    for (int r = r0 + warp * UNROLL; r < r1; r += NW * UNROLL) {
        float v[UNROLL];
        int lb[UNROLL];
#pragma unroll
        for (int u = 0; u < UNROLL; u++) {
            int rr = r + u;
            if (rr < r1) {
                v[u] = base[(size_t)rr * DD];
                lb[u] = lab32[rr * stride];
            } else {
                lb[u] = -1;
                v[u] = 0.f;
            }
        }
#pragma unroll
        for (int u = 0; u < UNROLL; u++)
            if (lb[u] >= 0) atomicAdd(&tbl[lb[u] * COLS + lane], v[u]);
    }
    __syncthreads();

    // Non-atomic vectorized flush to partials (avoids global atomics).
    // tbl rows are 32 floats = 8 float4; dst rows (stride DD) are 16B aligned.
    float* dst = g_part + (size_t)blockIdx.y * CC * DD + col0;
    const float4* t4 = (const float4*)tbl;
    for (int i = threadIdx.x; i < CC * (COLS / 4); i += blockDim.x) {
        int c = i >> 3;          // i / 8
        int q = i & 7;           // float4 index within row
        ((float4*)(dst + (size_t)c * DD))[q] = t4[i];
    }
}

// --- reduce partials -> g_sums, accumulate g_total ------------------------
__global__ void kReduce() {
    const int c = blockIdx.x;
    for (int d = threadIdx.x; d < DD; d += blockDim.x) {
        float s = 0.f;
#pragma unroll
        for (int y = 0; y < YS; y++)
            s += g_part[((size_t)y * CC + c) * DD + d];
        g_sums[c * DD + d] = s;
        atomicAdd(&g_total[d], s);
    }
}

// --- per-class distance + loss accumulation -------------------------------
__global__ void kFinal() {
    const int c = blockIdx.x;
    const float cnt = (float)g_cnts[c];
    __shared__ float red[NW];
    float acc = 0.f;
    if (cnt > 0.f) {
        float alpha = 1.f / cnt + 1.f / ((float)NN - cnt);
        float beta = 1.f / ((float)NN - cnt);
        for (int d = threadIdx.x; d < DD; d += blockDim.x) {
            float v = alpha * g_sums[c * DD + d] - beta * g_total[d] + EPSV;
            acc += v * v;
        }
    }
#pragma unroll
    for (int o = 16; o; o >>= 1) acc += __shfl_xor_sync(0xFFFFFFFFu, acc, o);
    if ((threadIdx.x & 31) == 0) red[threadIdx.x >> 5] = acc;
    __syncthreads();
    if (threadIdx.x < NW) {
        float a = red[threadIdx.x];
#pragma unroll
        for (int o = NW / 2; o; o >>= 1) a += __shfl_xor_sync(0xFFu, a, o);
        if (threadIdx.x == 0 && cnt > 0.f) {
            float dist = sqrtf(a);
            float m = fmaxf(MARGINV - dist, 0.f);
            atomicAdd(&g_loss, cnt * m * m);
        }
    }
}

__global__ void kOut(float* __restrict__ res) {
    res[0] = g_loss * (1.f / (float)NN);
}

// ---------------------------------------------------------------------------
extern "C" void kernel_launch(void* const* d_in, const int* in_sizes, int n_in,
                              void* d_out, int out_size) {
    const float* out = (const float*)d_in[0];
    const int* lab32 = (const int*)d_in[1];  // int32 view; stride handles int64
    float* res = (float*)d_out;

    cudaFuncSetAttribute(kSegSum, cudaFuncAttributeMaxDynamicSharedMemorySize,
                         SEG_SMEM);
    cudaFuncSetAttribute(kSegSum,
                         cudaFuncAttributePreferredSharedMemoryCarveout, 100);

    kInit<<<1, 512>>>(lab32);
    kHist<<<32, 256>>>(lab32);
    dim3 grid(CHUNKS, YS);
    kSegSum<<<grid, NW * 32, SEG_SMEM>>>(out, lab32);
    kReduce<<<CC, 256>>>();
    kFinal<<<CC, NW * 32>>>();
    kOut<<<1, 1>>>(res);
}

// round 3
// speedup vs baseline: 1.3082x; 1.3082x over previous
#include <cuda_runtime.h>
#include <cuda_bf16.h>
#include <math.h>

// ---------------------------------------------------------------------------
// ScatterLoss: loss depends only on per-class statistics.
//   s_c = sum of rows with label c   (C x D)
//   total = sum over all rows        (D)
//   v_c[d] = alpha_c * s_c[d] - beta_c * total[d] + EPS
//   loss = (1/N) * sum_c cnt_c * max(1 - ||v_c||, 0)^2
//
// v3: counting-sort row ownership -> register accumulation, no smem atomics.
// ---------------------------------------------------------------------------

#define NN 65536
#define DD 512
#define CC 512
#define EPSV 1e-6f
#define MARGINV 1.0f
#define SPLIT 4                       // row-splits per class

// Scratch (device globals: allocation-free per harness rules)
__device__ float g_part[(size_t)SPLIT * CC * DD];   // 4 MB partial class sums
__device__ float g_total[DD];
__device__ int   g_cnts[CC];
__device__ int   g_off[CC + 1];
__device__ int   g_fill[CC];
__device__ int   g_sorted[NN];
__device__ float g_loss;
__device__ int   g_lab_stride;        // 1 = int32 labels, 2 = int64

// --- init: zero accumulators + detect label dtype -------------------------
__global__ void kInit(const int* __restrict__ lab32) {
    int t = threadIdx.x;
    if (t < CC) g_cnts[t] = 0;
    if (t == 0) g_loss = 0.f;
    // int64 LE: element i -> lab32[2i] lo, lab32[2i+1] hi(==0 for labels<512).
    // 128 consecutive odd words all zero is impossible for int32 random labels.
    int nz = (t < 128) ? lab32[2 * t + 1] : 0;
    int any = __syncthreads_or(nz);
    if (t == 0) g_lab_stride = any ? 1 : 2;
}

// --- histogram of labels ---------------------------------------------------
__global__ void kHist(const int* __restrict__ lab32) {
    __shared__ int h[CC];
    for (int i = threadIdx.x; i < CC; i += blockDim.x) h[i] = 0;
    __syncthreads();
    const int stride = g_lab_stride;
    for (int i = blockIdx.x * blockDim.x + threadIdx.x; i < NN;
         i += gridDim.x * blockDim.x)
        atomicAdd(&h[lab32[i * stride]], 1);
    __syncthreads();
    for (int i = threadIdx.x; i < CC; i += blockDim.x)
        if (h[i]) atomicAdd(&g_cnts[i], h[i]);
}

// --- exclusive scan of counts (1 block, 512 threads) ----------------------
__global__ void kScan() {
    __shared__ int tmp[CC];
    int t = threadIdx.x;
    tmp[t] = g_cnts[t];
    __syncthreads();
#pragma unroll
    for (int o = 1; o < CC; o <<= 1) {
        int v = (t >= o) ? tmp[t - o] : 0;
        __syncthreads();
        tmp[t] += v;
        __syncthreads();
    }
    g_off[t + 1] = tmp[t];
    if (t == 0) g_off[0] = 0;
    g_fill[t] = 0;
}

// --- scatter row indices into class-sorted order --------------------------
__global__ void kScatter(const int* __restrict__ lab32) {
    const int stride = g_lab_stride;
    for (int i = blockIdx.x * blockDim.x + threadIdx.x; i < NN;
         i += gridDim.x * blockDim.x) {
        int c = lab32[i * stride];
        int pos = atomicAdd(&g_fill[c], 1);
        g_sorted[g_off[c] + pos] = i;
    }
}

// --- segment sums: register accumulation, zero atomics --------------------
// grid = CC*SPLIT blocks, 128 threads. Thread t owns cols [4t, 4t+4).
__global__ void kSegSum(const float* __restrict__ out) {
    const int b = blockIdx.x;
    const int c = b >> 2;
    const int p = b & (SPLIT - 1);
    const int start = g_off[c], end = g_off[c + 1];
    const int n = end - start;
    const int chunk = (n + SPLIT - 1) / SPLIT;
    const int lo = start + p * chunk;
    const int hi = min(lo + chunk, end);
    const int t = threadIdx.x;
    const float4* __restrict__ src = (const float4*)out;

    float4 acc = make_float4(0.f, 0.f, 0.f, 0.f);
    int r = lo;
    for (; r + 4 <= hi; r += 4) {
        int i0 = g_sorted[r + 0], i1 = g_sorted[r + 1];
        int i2 = g_sorted[r + 2], i3 = g_sorted[r + 3];
        float4 a = src[(size_t)i0 * (DD / 4) + t];
        float4 bb = src[(size_t)i1 * (DD / 4) + t];
        float4 cc = src[(size_t)i2 * (DD / 4) + t];
        float4 dd = src[(size_t)i3 * (DD / 4) + t];
        acc.x += (a.x + bb.x) + (cc.x + dd.x);
        acc.y += (a.y + bb.y) + (cc.y + dd.y);
        acc.z += (a.z + bb.z) + (cc.z + dd.z);
        acc.w += (a.w + bb.w) + (cc.w + dd.w);
    }
    for (; r < hi; r++) {
        float4 a = src[(size_t)g_sorted[r] * (DD / 4) + t];
        acc.x += a.x; acc.y += a.y; acc.z += a.z; acc.w += a.w;
    }
    ((float4*)(g_part + ((size_t)p * CC + c) * DD))[t] = acc;
}

// --- total[d] = sum over all partials (coalesced) -------------------------
// grid = 16 blocks x 256 threads; block j covers d in [32j, 32j+32).
__global__ void kTotal() {
    const int lane = threadIdx.x & 31;
    const int w = threadIdx.x >> 5;
    const int d = blockIdx.x * 32 + lane;
    float s = 0.f;
    for (int row = w; row < SPLIT * CC; row += 8)
        s += g_part[(size_t)row * DD + d];
    __shared__ float red[8][32];
    red[w][lane] = s;
    __syncthreads();
    if (w == 0) {
        float a = red[0][lane];
#pragma unroll
        for (int k = 1; k < 8; k++) a += red[k][lane];
        g_total[d] = a;
    }
}

// --- per-class distance + loss (512 blocks, 128 threads) ------------------
__global__ void kFinal() {
    const int c = blockIdx.x;
    const float cnt = (float)g_cnts[c];
    const int t = threadIdx.x;
    float acc = 0.f;
    if (cnt > 0.f) {
        const float alpha = 1.f / cnt + 1.f / ((float)NN - cnt);
        const float beta = 1.f / ((float)NN - cnt);
        float4 s = make_float4(0.f, 0.f, 0.f, 0.f);
#pragma unroll
        for (int p = 0; p < SPLIT; p++) {
            float4 a = ((const float4*)(g_part + ((size_t)p * CC + c) * DD))[t];
            s.x += a.x; s.y += a.y; s.z += a.z; s.w += a.w;
        }
        float4 tt = ((const float4*)g_total)[t];
        float vx = alpha * s.x - beta * tt.x + EPSV;
        float vy = alpha * s.y - beta * tt.y + EPSV;
        float vz = alpha * s.z - beta * tt.z + EPSV;
        float vw = alpha * s.w - beta * tt.w + EPSV;
        acc = vx * vx + vy * vy + vz * vz + vw * vw;
    }
#pragma unroll
    for (int o = 16; o; o >>= 1) acc += __shfl_xor_sync(0xFFFFFFFFu, acc, o);
    __shared__ float red[4];
    if ((t & 31) == 0) red[t >> 5] = acc;
    __syncthreads();
    if (t == 0 && cnt > 0.f) {
        float a = red[0] + red[1] + red[2] + red[3];
        float dist = sqrtf(a);
        float m = fmaxf(MARGINV - dist, 0.f);
        atomicAdd(&g_loss, cnt * m * m);
    }
}

__global__ void kOut(float* __restrict__ res) {
    res[0] = g_loss * (1.f / (float)NN);
}

// ---------------------------------------------------------------------------
extern "C" void kernel_launch(void* const* d_in, const int* in_sizes, int n_in,
                              void* d_out, int out_size) {
    const float* out = (const float*)d_in[0];
    const int* lab32 = (const int*)d_in[1];  // int32 view; stride handles int64
    float* res = (float*)d_out;

    kInit<<<1, 512>>>(lab32);
    kHist<<<32, 256>>>(lab32);
    kScan<<<1, 512>>>();
    kScatter<<<64, 256>>>(lab32);
    kSegSum<<<CC * SPLIT, 128>>>(out);
    kTotal<<<16, 256>>>();
    kFinal<<<CC, 128>>>();
    kOut<<<1, 1>>>(res);
}